// round 10
// baseline (speedup 1.0000x reference)
#include <cuda_runtime.h>
#include <math.h>

#define B_N    256
#define T_PAST 20
#define T_FUT  30
#define NT     256

// ---- shared memory layout (float indices) ----
#define SM_WT1   0        // 4*32*36  conv1 [kk][co][ci] stride 36
#define SM_WT2   4608
#define SM_WT3   9216
#define SM_WT0   13824    // 256
#define SM_CB    14080    // 128
#define SM_DWIH  14208    // 96*36
#define SM_DWHH  17664    // 96*36
#define SM_EWHH  21120    // 96*36
#define SM_WC    24576    // 128
#define SM_BC    24704    // 4
#define SM_A0    24708    // 800
#define SM_A1    25508    // 512
#define SM_A2    26020    // 288
#define SM_A3    26308    // 128
#define SM_X     26436    // 36
#define SM_H     26472    // 32
#define SM_GI    26504    // 96
#define SM_GH    26600    // 96
#define SM_Y     26696    // 4
#define SM_Q4    26700    // 4: f0,f1,ay,ax
#define SM_PP    26704    // 40
#define SM_ZB    26744    // 60
#define SM_EWIH  26804    // 192
#define SM_EBIH  26996    // 96
#define SM_EBHH  27092    // 96
#define SM_DBIH  27188    // 96
#define SM_DBHH  27284    // 96
#define SM_LD    27380    // 2
#define SM_TOTAL 27382
#define SMEM_BYTES (SM_TOTAL * 4)

typedef unsigned long long ull;

#define BARS(id, cnt) asm volatile("bar.sync %0, %1;" :: "n"(id), "n"(cnt) : "memory")

__device__ __forceinline__ void ffma2(ull& d, ull a, ull b) {
    asm("fma.rn.f32x2 %0, %1, %2, %0;" : "+l"(d) : "l"(a), "l"(b));
}
__device__ __forceinline__ float hsum2(ull v) {
    float lo, hi;
    asm("mov.b64 {%0,%1}, %2;" : "=f"(lo), "=f"(hi) : "l"(v));
    return lo + hi;
}
__device__ __forceinline__ float fexp2_(float x) {
    float r; asm("ex2.approx.f32 %0, %1;" : "=f"(r) : "f"(x)); return r;
}
__device__ __forceinline__ float flg2_(float x) {
    float r; asm("lg2.approx.f32 %0, %1;" : "=f"(r) : "f"(x)); return r;
}
__device__ __forceinline__ float frcp_(float x) {
    float r; asm("rcp.approx.f32 %0, %1;" : "=f"(r) : "f"(x)); return r;
}
__device__ __forceinline__ float ftanh_(float x) {
    float r; asm("tanh.approx.f32 %0, %1;" : "=f"(r) : "f"(x)); return r;
}
#define LOG2E 1.4426950408889634f
#define LN2   0.6931471805599453f
__device__ __forceinline__ float fsig_(float x) {
    return frcp_(1.f + fexp2_(-LOG2E * x));
}
__device__ __forceinline__ float flogf_(float x) { return flg2_(x) * LN2; }
__device__ __forceinline__ float fsoftplus_(float x) {
    return (x > 20.f) ? x : flg2_(1.f + fexp2_(LOG2E * x)) * LN2;
}

// Row-aligned conv tile with activation reuse.
// Computes CPW consecutive cells (r, c0..c0+CPW-1) of the output; lane = co.
// Inputs: rows r..r+1, cols c0..c0+CPW of the input (IS wide).
template <int OS, int IS, int CPW>
__device__ __forceinline__ void conv_row(const float* __restrict__ ain,
                                         float* __restrict__ aout,
                                         const float* __restrict__ wT,
                                         const float* __restrict__ bias,
                                         int r, int c0, int fy, int fx, int lane)
{
    ull acc[CPW][2];
    #pragma unroll
    for (int c = 0; c < CPW; ++c) { acc[c][0] = 0ULL; acc[c][1] = 0ULL; }

    const ulonglong2* wp[4];
    #pragma unroll
    for (int kk = 0; kk < 4; ++kk)
        wp[kk] = (const ulonglong2*)(wT + (kk * 32 + lane) * 36);

    const ulonglong2* ap[2][CPW + 1];
    #pragma unroll
    for (int kh = 0; kh < 2; ++kh)
        #pragma unroll
        for (int j = 0; j <= CPW; ++j)
            ap[kh][j] = (const ulonglong2*)(ain + ((r + kh) * IS + c0 + j) * 32);

    #pragma unroll
    for (int q = 0; q < 8; ++q) {
        ulonglong2 wv[4];
        #pragma unroll
        for (int kk = 0; kk < 4; ++kk) wv[kk] = wp[kk][q];
        #pragma unroll
        for (int kh = 0; kh < 2; ++kh) {
            #pragma unroll
            for (int j = 0; j <= CPW; ++j) {
                ulonglong2 av = ap[kh][j][q];
                if (j < CPW) {          // kw = 0 contribution to cell j
                    ffma2(acc[j][0], av.x, wv[kh * 2].x);
                    ffma2(acc[j][1], av.y, wv[kh * 2].y);
                }
                if (j >= 1) {           // kw = 1 contribution to cell j-1
                    ffma2(acc[j - 1][0], av.x, wv[kh * 2 + 1].x);
                    ffma2(acc[j - 1][1], av.y, wv[kh * 2 + 1].y);
                }
            }
        }
    }
    const float bl = bias[lane];
    #pragma unroll
    for (int c = 0; c < CPW; ++c) {
        float o = hsum2(acc[c][0]) + hsum2(acc[c][1]) + bl;
        o = fmaxf(o, 0.f);
        if (fy + r > 99 || fx + c0 + c > 99) o = 0.f;
        aout[(r * OS + c0 + c) * 32 + lane] = o;
    }
}

extern __shared__ float sm[];

__global__ void __launch_bounds__(NT, 2)
r2p2_kernel(const float* __restrict__ z,
            const float* __restrict__ pp,
            const float* __restrict__ lidar,
            const float* __restrict__ c0w, const float* __restrict__ c0b,
            const float* __restrict__ c1w, const float* __restrict__ c1b,
            const float* __restrict__ c2w, const float* __restrict__ c2b,
            const float* __restrict__ c3w, const float* __restrict__ c3b,
            const float* __restrict__ ewih, const float* __restrict__ ewhh,
            const float* __restrict__ ebih, const float* __restrict__ ebhh,
            const float* __restrict__ dwih, const float* __restrict__ dwhh,
            const float* __restrict__ dbih, const float* __restrict__ dbhh,
            const float* __restrict__ w1, const float* __restrict__ b1,
            const float* __restrict__ w2, const float* __restrict__ b2,
            float* __restrict__ out)
{
    const int b = blockIdx.x;
    const int tid = threadIdx.x;
    const int wid = tid >> 5, lane = tid & 31;

    float* WT1 = sm + SM_WT1;  float* WT2 = sm + SM_WT2;  float* WT3 = sm + SM_WT3;
    float* WT0 = sm + SM_WT0;  float* CB  = sm + SM_CB;
    float* DWIH = sm + SM_DWIH; float* DWHH = sm + SM_DWHH; float* EWHH = sm + SM_EWHH;
    float* WC = sm + SM_WC;    float* BC = sm + SM_BC;
    float* A0 = sm + SM_A0;  float* A1 = sm + SM_A1;  float* A2 = sm + SM_A2;
    float* A3 = sm + SM_A3;
    float* X = sm + SM_X;  float* H = sm + SM_H;
    float* GI = sm + SM_GI;   float* GH = sm + SM_GH;
    float* Y  = sm + SM_Y;    float* Q4 = sm + SM_Q4;
    float* PP = sm + SM_PP; float* ZB = sm + SM_ZB;
    float* EWIH = sm + SM_EWIH; float* EBIH = sm + SM_EBIH; float* EBHH = sm + SM_EBHH;
    float* DBIH = sm + SM_DBIH; float* DBHH = sm + SM_DBHH;
    float* LD = sm + SM_LD;

    const float* lidb = lidar + b * 20000;   // [100][100][2]

    // ---- setup ----
    {
        const float* srcs[3] = { c1w, c2w, c3w };
        float* dsts[3] = { WT1, WT2, WT3 };
        #pragma unroll
        for (int l = 0; l < 3; ++l) {
            const float* s = srcs[l]; float* d = dsts[l];
            for (int idx = tid; idx < 4096; idx += NT) {
                int co = idx & 31, ci = (idx >> 5) & 31, kk = idx >> 10;
                d[(kk * 32 + co) * 36 + ci] = s[idx];
            }
        }
        for (int idx = tid; idx < 256; idx += NT) {
            int co = idx & 31, ci = (idx >> 5) & 1, kk = idx >> 6;
            WT0[(kk * 32 + co) * 2 + ci] = c0w[idx];
        }
    }
    if (tid < 32) {
        CB[tid] = c0b[tid]; CB[32 + tid] = c1b[tid];
        CB[64 + tid] = c2b[tid]; CB[96 + tid] = c3b[tid];
    }
    for (int idx = tid; idx < 96 * 34; idx += NT) {
        int j = idx / 34, k = idx % 34;
        DWIH[j * 36 + k] = dwih[idx];
    }
    for (int idx = tid; idx < 96 * 32; idx += NT) {
        int j = idx >> 5, k = idx & 31;
        DWHH[j * 36 + k] = dwhh[idx];
        EWHH[j * 36 + k] = ewhh[idx];
    }
    if (tid < 96) {
        EWIH[tid * 2] = ewih[tid * 2]; EWIH[tid * 2 + 1] = ewih[tid * 2 + 1];
        EBIH[tid] = ebih[tid]; EBHH[tid] = ebhh[tid];
        DBIH[tid] = dbih[tid]; DBHH[tid] = dbhh[tid];
    }
    if (tid < 128) {
        int o = tid >> 5, i = tid & 31;
        const float* w2r = w2 + o * 512;
        float a0 = 0.f, a1 = 0.f;
        for (int k = 0; k < 512; k += 2) {
            a0 = fmaf(w2r[k + 0], w1[(k + 0) * 32 + i], a0);
            a1 = fmaf(w2r[k + 1], w1[(k + 1) * 32 + i], a1);
        }
        WC[tid] = a0 + a1;
    } else {
        int o = (tid - 128) >> 5, l = tid & 31;
        float acc = 0.f;
        for (int k = l; k < 512; k += 32) acc = fmaf(w2[o * 512 + k], b1[k], acc);
        #pragma unroll
        for (int off = 16; off; off >>= 1)
            acc += __shfl_xor_sync(0xffffffffu, acc, off);
        if (l == 0) BC[o] = acc + b2[o];
    }
    if (tid < 40) PP[tid] = pp[b * (T_PAST * 2) + tid];
    if (tid < 60) ZB[tid] = z[b * (T_FUT * 2) + tid];
    if (tid < 32) H[tid] = 0.f;
    if (tid < 2) {
        Y[tid]     = pp[(b * T_PAST + 19) * 2 + tid];   // y_{t-1}
        Y[2 + tid] = pp[(b * T_PAST + 18) * 2 + tid];   // y_{t-2}
    }
    __syncthreads();

    // ---- encoder GRU: 20 steps in warps 0-2 (named barrier 3) ----
    if (tid < 96) {
        for (int t = 0; t < T_PAST; ++t) {
            float x0 = PP[t * 2], x1 = PP[t * 2 + 1];
            float gi = EBIH[tid] + x0 * EWIH[tid * 2] + x1 * EWIH[tid * 2 + 1];
            ull g0 = 0ULL, g1 = 0ULL;
            const ulonglong2* wr = (const ulonglong2*)(EWHH + tid * 36);
            const ulonglong2* hp = (const ulonglong2*)H;
            #pragma unroll
            for (int k = 0; k < 8; ++k) {
                ulonglong2 wv = wr[k];
                ulonglong2 hv = hp[k];
                ffma2(g0, hv.x, wv.x);
                ffma2(g1, hv.y, wv.y);
            }
            GI[tid] = gi;
            GH[tid] = EBHH[tid] + hsum2(g0) + hsum2(g1);
            BARS(3, 96);
            if (tid < 32) {
                float r  = fsig_(GI[tid] + GH[tid]);
                float zg = fsig_(GI[32 + tid] + GH[32 + tid]);
                float n  = ftanh_(GI[64 + tid] + r * GH[64 + tid]);
                H[tid] = (1.f - zg) * n + zg * H[tid];
            }
            BARS(3, 96);
        }
    }
    __syncthreads();

    // ---- prologue: GH for t=0 + Q4 coords from initial Y ----
    if (tid < 96) {
        ull g0 = 0ULL, g1 = 0ULL;
        const ulonglong2* hr = (const ulonglong2*)(DWHH + tid * 36);
        const ulonglong2* hp = (const ulonglong2*)H;
        #pragma unroll
        for (int k = 0; k < 8; ++k) {
            ulonglong2 wv = hr[k];
            ulonglong2 hv = hp[k];
            ffma2(g0, hv.x, wv.x);
            ffma2(g1, hv.y, wv.y);
        }
        GH[tid] = DBHH[tid] + hsum2(g0) + hsum2(g1);
    } else if (tid == 96) {
        float q0c = Y[0], q1c = Y[1];
        float f0 = fminf(fmaxf(floorf(q0c), 0.f), 98.f);
        float f1 = fminf(fmaxf(floorf(q1c), 0.f), 98.f);
        Q4[0] = f0; Q4[1] = f1;
        Q4[2] = fminf(fmaxf(q0c - f0, 0.f), 1.f);
        Q4[3] = fminf(fmaxf(q1c - f1, 0.f), 1.f);
    }
    __syncthreads();

    // ---- decoder: 30 autoregressive steps ----
    float logdet = 0.f;   // accumulated in tid 0,1
    for (int t = 0; t < T_FUT; ++t) {
        const int fy = (int)Q4[0], fx = (int)Q4[1];

        // P1: layer0 — 800 outputs, lidar read straight from global (L1-cached)
        for (int idx = tid; idx < 800; idx += NT) {
            int co = idx & 31, cell = idx >> 5;
            int r = cell / 5, c = cell % 5;
            ull acc = 0ULL;
            #pragma unroll
            for (int kk = 0; kk < 4; ++kk) {
                int kh = kk >> 1, kw = kk & 1;
                int gy = fy + r + kh, gx = fx + c + kw;
                ull lv = 0ULL;
                if (gy < 100 && gx < 100)
                    lv = *(const ull*)(lidb + (gy * 100 + gx) * 2);
                ull wv = *(const ull*)(WT0 + (kk * 32 + co) * 2);
                ffma2(acc, lv, wv);
            }
            float o = fmaxf(hsum2(acc) + CB[co], 0.f);
            if (fy + r > 99 || fx + c > 99) o = 0.f;
            A0[cell * 32 + co] = o;
        }
        __syncthreads();

        // P2: layer1 (5->4): 8 warps x 2 row-cells
        conv_row<4, 5, 2>(A0, A1, WT1, CB + 32, wid >> 1, (wid & 1) * 2,
                          fy, fx, lane);
        __syncthreads();

        // P3: layer2 (4->3): 6 warps (even: 2 cells, odd: 1 cell)
        if (wid < 6) {
            int r = wid >> 1;
            if (wid & 1)
                conv_row<3, 4, 1>(A1, A2, WT2, CB + 64, r, 2, fy, fx, lane);
            else
                conv_row<3, 4, 2>(A1, A2, WT2, CB + 64, r, 0, fy, fx, lane);
        }
        __syncthreads();

        // P4: layer3 (3->2): 4 warps x 1 cell, then warp 0 bilinear -> X
        if (tid < 128) {
            conv_row<2, 3, 1>(A2, A3, WT3, CB + 96, wid >> 1, wid & 1,
                              fy, fx, lane);
            BARS(1, 128);
            if (wid == 0) {
                float ay = Q4[2], ax = Q4[3];
                float tl = A3[lane], tr = A3[32 + lane];
                float bl = A3[64 + lane], br = A3[96 + lane];
                float top = tl + ax * (tr - tl);
                float bot = bl + ax * (br - bl);
                X[2 + lane] = top + ay * (bot - top);
                if (lane < 2) X[lane] = Y[lane];
            }
        }
        __syncthreads();

        // P5: GI -> gates/H -> (GH for next step || head/Y-update)
        if (tid < 96) {
            ull a0 = 0ULL, a1 = 0ULL;
            const ulonglong2* wr = (const ulonglong2*)(DWIH + tid * 36);
            const ulonglong2* xp = (const ulonglong2*)X;
            #pragma unroll
            for (int k = 0; k < 8; ++k) {
                ulonglong2 wv = wr[k];
                ulonglong2 xv = xp[k];
                ffma2(a0, xv.x, wv.x);
                ffma2(a1, xv.y, wv.y);
            }
            ull wl = *(const ull*)(DWIH + tid * 36 + 32);
            ull xl = *(const ull*)(X + 32);
            ffma2(a0, xl, wl);
            GI[tid] = DBIH[tid] + hsum2(a0) + hsum2(a1);
            BARS(2, 96);

            if (tid < 32) {
                float r  = fsig_(GI[tid] + GH[tid]);
                float zg = fsig_(GI[32 + tid] + GH[32 + tid]);
                float n  = ftanh_(GI[64 + tid] + r * GH[64 + tid]);
                H[tid] = (1.f - zg) * n + zg * H[tid];
            }
            BARS(2, 96);

            // GH for next step (uses updated H)
            ull g0 = 0ULL, g1 = 0ULL;
            const ulonglong2* hr = (const ulonglong2*)(DWHH + tid * 36);
            const ulonglong2* hp = (const ulonglong2*)H;
            #pragma unroll
            for (int k = 0; k < 8; ++k) {
                ulonglong2 wv = hr[k];
                ulonglong2 hv = hp[k];
                ffma2(g0, hv.x, wv.x);
                ffma2(g1, hv.y, wv.y);
            }
            GH[tid] = DBHH[tid] + hsum2(g0) + hsum2(g1);

            if (tid < 32) {
                // warp-parallel head: 4 outputs x 32 features (8 lanes each)
                int o = tid >> 3, k0 = (tid & 7) * 4;
                const float* wr2 = WC + o * 32 + k0;
                const float* hr2 = H + k0;
                float part = wr2[0] * hr2[0];
                part = fmaf(wr2[1], hr2[1], part);
                part = fmaf(wr2[2], hr2[2], part);
                part = fmaf(wr2[3], hr2[3], part);
                #pragma unroll
                for (int off = 4; off; off >>= 1)
                    part += __shfl_xor_sync(0xffffffffu, part, off);
                float v = part + BC[o];
                float locv = __shfl_sync(0xffffffffu, v, (tid & 1) * 8);
                float spv  = __shfl_sync(0xffffffffu, v, 16 + (tid & 1) * 8);
                float yn = 0.f;
                if (tid < 2) {
                    float s  = fsoftplus_(spv);
                    float zt = ZB[t * 2 + tid];
                    yn = 2.f * Y[tid] - Y[2 + tid] + locv + s * zt;
                    out[(b * T_FUT + t) * 2 + tid] = yn;
                    logdet += flogf_(s);
                    Y[2 + tid] = Y[tid];
                    Y[tid] = yn;
                }
                float y0 = __shfl_sync(0xffffffffu, yn, 0);
                float y1 = __shfl_sync(0xffffffffu, yn, 1);
                if (tid == 0) {
                    float f0 = fminf(fmaxf(floorf(y0), 0.f), 98.f);
                    float f1 = fminf(fmaxf(floorf(y1), 0.f), 98.f);
                    Q4[0] = f0; Q4[1] = f1;
                    Q4[2] = fminf(fmaxf(y0 - f0, 0.f), 1.f);
                    Q4[3] = fminf(fmaxf(y1 - f1, 0.f), 1.f);
                }
            }
        }
        __syncthreads();   // Y/H/GH/Q4 ready for next step
    }

    if (tid < 2) LD[tid] = logdet;
    __syncthreads();
    if (tid == 0) out[B_N * T_FUT * 2 + b] = LD[0] + LD[1];
}

extern "C" void kernel_launch(void* const* d_in, const int* in_sizes, int n_in,
                              void* d_out, int out_size)
{
    const float* z    = (const float*)d_in[0];
    const float* pp   = (const float*)d_in[1];
    const float* lid  = (const float*)d_in[2];
    const float* c0w  = (const float*)d_in[3];
    const float* c0b  = (const float*)d_in[4];
    const float* c1w  = (const float*)d_in[5];
    const float* c1b  = (const float*)d_in[6];
    const float* c2w  = (const float*)d_in[7];
    const float* c2b  = (const float*)d_in[8];
    const float* c3w  = (const float*)d_in[9];
    const float* c3b  = (const float*)d_in[10];
    const float* ewih = (const float*)d_in[11];
    const float* ewhh = (const float*)d_in[12];
    const float* ebih = (const float*)d_in[13];
    const float* ebhh = (const float*)d_in[14];
    const float* dwih = (const float*)d_in[15];
    const float* dwhh = (const float*)d_in[16];
    const float* dbih = (const float*)d_in[17];
    const float* dbhh = (const float*)d_in[18];
    const float* w1   = (const float*)d_in[19];
    const float* b1   = (const float*)d_in[20];
    const float* w2   = (const float*)d_in[21];
    const float* b2   = (const float*)d_in[22];
    float* out = (float*)d_out;

    cudaFuncSetAttribute(r2p2_kernel,
                         cudaFuncAttributeMaxDynamicSharedMemorySize, SMEM_BYTES);

    r2p2_kernel<<<B_N, NT, SMEM_BYTES>>>(z, pp, lid,
        c0w, c0b, c1w, c1b, c2w, c2b, c3w, c3b,
        ewih, ewhh, ebih, ebhh, dwih, dwhh, dbih, dbhh,
        w1, b1, w2, b2, out);
}

// round 11
// speedup vs baseline: 1.4522x; 1.4522x over previous
#include <cuda_runtime.h>
#include <math.h>

#define B_N    256
#define T_PAST 20
#define T_FUT  30
#define NT     256

// ---- shared memory layout (float indices) ----
#define SM_DWIH  0        // 96*36
#define SM_DWHH  3456     // 96*36
#define SM_EWHH  6912     // 96*36
#define SM_WC    10368    // 128
#define SM_BC    10496    // 4
#define SM_A0    10500    // 800
#define SM_A1    11300    // 512
#define SM_A2    11812    // 288
#define SM_P1    12100    // 16*4*32 = 2048
#define SM_P2    14148    // 9*4*32 = 1152
#define SM_P3    15300    // 4*4*32 = 512
#define SM_X     15812    // 36
#define SM_H     15848    // 32
#define SM_GI    15880    // 96
#define SM_GH    15976    // 96
#define SM_Y     16072    // 4
#define SM_Q4    16076    // 4
#define SM_PP    16080    // 40
#define SM_ZB    16120    // 60
#define SM_EWIH  16180    // 192
#define SM_EBIH  16372    // 96
#define SM_EBHH  16468    // 96
#define SM_DBIH  16564    // 96
#define SM_DBHH  16660    // 96
#define SM_LD    16756    // 2
#define SM_TOTAL 16758
#define SMEM_BYTES (SM_TOTAL * 4)

typedef unsigned long long ull;

#define BARS(id, cnt) asm volatile("bar.sync %0, %1;" :: "n"(id), "n"(cnt) : "memory")

__device__ __forceinline__ void ffma2(ull& d, ull a, ull b) {
    asm("fma.rn.f32x2 %0, %1, %2, %0;" : "+l"(d) : "l"(a), "l"(b));
}
__device__ __forceinline__ float hsum2(ull v) {
    float lo, hi;
    asm("mov.b64 {%0,%1}, %2;" : "=f"(lo), "=f"(hi) : "l"(v));
    return lo + hi;
}
__device__ __forceinline__ ull pack2(float lo, float hi) {
    ull r; asm("mov.b64 %0, {%1, %2};" : "=l"(r) : "f"(lo), "f"(hi)); return r;
}
__device__ __forceinline__ float fexp2_(float x) {
    float r; asm("ex2.approx.f32 %0, %1;" : "=f"(r) : "f"(x)); return r;
}
__device__ __forceinline__ float flg2_(float x) {
    float r; asm("lg2.approx.f32 %0, %1;" : "=f"(r) : "f"(x)); return r;
}
__device__ __forceinline__ float frcp_(float x) {
    float r; asm("rcp.approx.f32 %0, %1;" : "=f"(r) : "f"(x)); return r;
}
__device__ __forceinline__ float ftanh_(float x) {
    float r; asm("tanh.approx.f32 %0, %1;" : "=f"(r) : "f"(x)); return r;
}
#define LOG2E 1.4426950408889634f
#define LN2   0.6931471805599453f
__device__ __forceinline__ float fsig_(float x) {
    return frcp_(1.f + fexp2_(-LOG2E * x));
}
__device__ __forceinline__ float flogf_(float x) { return flg2_(x) * LN2; }
__device__ __forceinline__ float fsoftplus_(float x) {
    return (x > 20.f) ? x : flg2_(1.f + fexp2_(LOG2E * x)) * LN2;
}

extern __shared__ float sm[];

__global__ void __launch_bounds__(NT, 2)
r2p2_kernel(const float* __restrict__ z,
            const float* __restrict__ pp,
            const float* __restrict__ lidar,
            const float* __restrict__ c0w, const float* __restrict__ c0b,
            const float* __restrict__ c1w, const float* __restrict__ c1b,
            const float* __restrict__ c2w, const float* __restrict__ c2b,
            const float* __restrict__ c3w, const float* __restrict__ c3b,
            const float* __restrict__ ewih, const float* __restrict__ ewhh,
            const float* __restrict__ ebih, const float* __restrict__ ebhh,
            const float* __restrict__ dwih, const float* __restrict__ dwhh,
            const float* __restrict__ dbih, const float* __restrict__ dbhh,
            const float* __restrict__ w1, const float* __restrict__ b1,
            const float* __restrict__ w2, const float* __restrict__ b2,
            float* __restrict__ out)
{
    const int b = blockIdx.x;
    const int tid = threadIdx.x;
    const int wid = tid >> 5, lane = tid & 31;

    float* DWIH = sm + SM_DWIH; float* DWHH = sm + SM_DWHH; float* EWHH = sm + SM_EWHH;
    float* WC = sm + SM_WC;    float* BC = sm + SM_BC;
    float* A0 = sm + SM_A0;  float* A1 = sm + SM_A1;  float* A2 = sm + SM_A2;
    float* P1 = sm + SM_P1;  float* P2 = sm + SM_P2;  float* P3 = sm + SM_P3;
    float* X = sm + SM_X;  float* H = sm + SM_H;
    float* GI = sm + SM_GI;   float* GH = sm + SM_GH;
    float* Y  = sm + SM_Y;    float* Q4 = sm + SM_Q4;
    float* PP = sm + SM_PP; float* ZB = sm + SM_ZB;
    float* EWIH = sm + SM_EWIH; float* EBIH = sm + SM_EBIH; float* EBHH = sm + SM_EBHH;
    float* DBIH = sm + SM_DBIH; float* DBHH = sm + SM_DBHH;
    float* LD = sm + SM_LD;

    const float* lidb = lidar + b * 20000;   // [100][100][2]

    // ---- register-resident weights ----
    const int kkA = wid & 3;           // this warp's kk slice (all layers)
    ull wr1[16];                       // conv1 [kkA][ci0..31][co=lane]
    ull wrB[16];                       // conv3 (warps 0-3) / conv2 (warps 4-7)
    ull w0r[4];                        // conv0 [kk][ci0..1][co=lane]
    {
        const float* srcB = (wid < 4) ? c3w : c2w;
        #pragma unroll
        for (int q = 0; q < 16; ++q) {
            wr1[q] = pack2(c1w[(kkA * 32 + 2 * q) * 32 + lane],
                           c1w[(kkA * 32 + 2 * q + 1) * 32 + lane]);
            wrB[q] = pack2(srcB[(kkA * 32 + 2 * q) * 32 + lane],
                           srcB[(kkA * 32 + 2 * q + 1) * 32 + lane]);
        }
        #pragma unroll
        for (int kk = 0; kk < 4; ++kk)
            w0r[kk] = pack2(c0w[(kk * 2 + 0) * 32 + lane],
                            c0w[(kk * 2 + 1) * 32 + lane]);
    }
    const float b0r = c0b[lane], b1r = c1b[lane];
    const float b2r = c2b[lane], b3r = c3b[lane];

    // ---- setup: GRU weights to smem + fused MLP collapse ----
    for (int idx = tid; idx < 96 * 34; idx += NT) {
        int j = idx / 34, k = idx % 34;
        DWIH[j * 36 + k] = dwih[idx];
    }
    for (int idx = tid; idx < 96 * 32; idx += NT) {
        int j = idx >> 5, k = idx & 31;
        DWHH[j * 36 + k] = dwhh[idx];
        EWHH[j * 36 + k] = ewhh[idx];
    }
    if (tid < 96) {
        EWIH[tid * 2] = ewih[tid * 2]; EWIH[tid * 2 + 1] = ewih[tid * 2 + 1];
        EBIH[tid] = ebih[tid]; EBHH[tid] = ebhh[tid];
        DBIH[tid] = dbih[tid]; DBHH[tid] = dbhh[tid];
    }
    if (tid < 128) {
        int o = tid >> 5, i = tid & 31;
        const float* w2r = w2 + o * 512;
        float a0 = 0.f, a1 = 0.f;
        for (int k = 0; k < 512; k += 2) {
            a0 = fmaf(w2r[k + 0], w1[(k + 0) * 32 + i], a0);
            a1 = fmaf(w2r[k + 1], w1[(k + 1) * 32 + i], a1);
        }
        WC[tid] = a0 + a1;
    } else {
        int o = (tid - 128) >> 5, l = tid & 31;
        float acc = 0.f;
        for (int k = l; k < 512; k += 32) acc = fmaf(w2[o * 512 + k], b1[k], acc);
        #pragma unroll
        for (int off = 16; off; off >>= 1)
            acc += __shfl_xor_sync(0xffffffffu, acc, off);
        if (l == 0) BC[o] = acc + b2[o];
    }
    if (tid < 40) PP[tid] = pp[b * (T_PAST * 2) + tid];
    if (tid < 60) ZB[tid] = z[b * (T_FUT * 2) + tid];
    if (tid < 32) H[tid] = 0.f;
    if (tid < 2) {
        Y[tid]     = pp[(b * T_PAST + 19) * 2 + tid];   // y_{t-1}
        Y[2 + tid] = pp[(b * T_PAST + 18) * 2 + tid];   // y_{t-2}
    }
    __syncthreads();

    // ---- encoder GRU: 20 steps in warps 0-2 (named barrier 3) ----
    if (tid < 96) {
        for (int t = 0; t < T_PAST; ++t) {
            float x0 = PP[t * 2], x1 = PP[t * 2 + 1];
            float gi = EBIH[tid] + x0 * EWIH[tid * 2] + x1 * EWIH[tid * 2 + 1];
            ull g0 = 0ULL, g1 = 0ULL;
            const ulonglong2* wr = (const ulonglong2*)(EWHH + tid * 36);
            const ulonglong2* hp = (const ulonglong2*)H;
            #pragma unroll
            for (int k = 0; k < 8; ++k) {
                ulonglong2 wv = wr[k];
                ulonglong2 hv = hp[k];
                ffma2(g0, hv.x, wv.x);
                ffma2(g1, hv.y, wv.y);
            }
            GI[tid] = gi;
            GH[tid] = EBHH[tid] + hsum2(g0) + hsum2(g1);
            BARS(3, 96);
            if (tid < 32) {
                float r  = fsig_(GI[tid] + GH[tid]);
                float zg = fsig_(GI[32 + tid] + GH[32 + tid]);
                float n  = ftanh_(GI[64 + tid] + r * GH[64 + tid]);
                H[tid] = (1.f - zg) * n + zg * H[tid];
            }
            BARS(3, 96);
        }
    }
    __syncthreads();

    // ---- prologue: GH for t=0 + Q4 coords from initial Y ----
    if (tid < 96) {
        ull g0 = 0ULL, g1 = 0ULL;
        const ulonglong2* hr = (const ulonglong2*)(DWHH + tid * 36);
        const ulonglong2* hp = (const ulonglong2*)H;
        #pragma unroll
        for (int k = 0; k < 8; ++k) {
            ulonglong2 wv = hr[k];
            ulonglong2 hv = hp[k];
            ffma2(g0, hv.x, wv.x);
            ffma2(g1, hv.y, wv.y);
        }
        GH[tid] = DBHH[tid] + hsum2(g0) + hsum2(g1);
    } else if (tid == 96) {
        float q0c = Y[0], q1c = Y[1];
        float f0 = fminf(fmaxf(floorf(q0c), 0.f), 98.f);
        float f1 = fminf(fmaxf(floorf(q1c), 0.f), 98.f);
        Q4[0] = f0; Q4[1] = f1;
        Q4[2] = fminf(fmaxf(q0c - f0, 0.f), 1.f);
        Q4[3] = fminf(fmaxf(q1c - f1, 0.f), 1.f);
    }
    __syncthreads();

    const int khA = kkA >> 1, kwA = kkA & 1;

    // ---- decoder: 30 autoregressive steps ----
    float logdet = 0.f;   // accumulated in tid 0,1
    for (int t = 0; t < T_FUT; ++t) {
        const int fy = (int)Q4[0], fx = (int)Q4[1];

        // P1: layer0 — 800 outputs, lidar from gmem (L1-cached), weights in regs
        for (int idx = tid; idx < 800; idx += NT) {
            int cell = idx >> 5;
            int r = cell / 5, c = cell % 5;
            ull acc = 0ULL;
            #pragma unroll
            for (int kk = 0; kk < 4; ++kk) {
                int kh = kk >> 1, kw = kk & 1;
                int gy = fy + r + kh, gx = fx + c + kw;
                ull lv = 0ULL;
                if (gy < 100 && gx < 100)
                    lv = *(const ull*)(lidb + (gy * 100 + gx) * 2);
                ffma2(acc, lv, w0r[kk]);
            }
            float o = fmaxf(hsum2(acc) + b0r, 0.f);
            if (fy + r > 99 || fx + c > 99) o = 0.f;
            A0[cell * 32 + lane] = o;
        }
        __syncthreads();

        // P2: layer1 partials — 8 warps, kk = wid&3, 2x4 cell block each
        {
            const int rbase = (wid >> 2) * 2;
            const ulonglong2* base1 =
                (const ulonglong2*)(A0 + ((rbase + khA) * 5 + kwA) * 32);
            ull acc[8];
            #pragma unroll
            for (int c8 = 0; c8 < 8; ++c8) acc[c8] = 0ULL;
            #pragma unroll
            for (int q = 0; q < 8; ++q) {
                #pragma unroll
                for (int c8 = 0; c8 < 8; ++c8) {
                    ulonglong2 av = base1[((c8 >> 2) * 5 + (c8 & 3)) * 8 + q];
                    ffma2(acc[c8], av.x, wr1[2 * q]);
                    ffma2(acc[c8], av.y, wr1[2 * q + 1]);
                }
            }
            #pragma unroll
            for (int c8 = 0; c8 < 8; ++c8)
                P1[(rbase * 4 + c8) * 128 + kkA * 32 + lane] = hsum2(acc[c8]);
        }
        __syncthreads();

        // P3: layer1 reduce — 512 outs, +bias+relu+bounds -> A1
        #pragma unroll
        for (int rep = 0; rep < 2; ++rep) {
            int cell = wid + rep * 8;
            const float* p = P1 + cell * 128 + lane;
            float s = (p[0] + p[32]) + (p[64] + p[96]) + b1r;
            s = fmaxf(s, 0.f);
            int r = cell >> 2, c = cell & 3;
            if (fy + r > 99 || fx + c > 99) s = 0.f;
            A1[cell * 32 + lane] = s;
        }
        __syncthreads();

        // P4: layer2 partials — warps 4-7 (kk = wid&3), all 9 cells
        if (wid >= 4) {
            const ulonglong2* base2 =
                (const ulonglong2*)(A1 + (khA * 4 + kwA) * 32);
            ull acc[9];
            #pragma unroll
            for (int c9 = 0; c9 < 9; ++c9) acc[c9] = 0ULL;
            #pragma unroll
            for (int q = 0; q < 8; ++q) {
                #pragma unroll
                for (int c9 = 0; c9 < 9; ++c9) {
                    ulonglong2 av = base2[((c9 / 3) * 4 + (c9 % 3)) * 8 + q];
                    ffma2(acc[c9], av.x, wrB[2 * q]);
                    ffma2(acc[c9], av.y, wrB[2 * q + 1]);
                }
            }
            #pragma unroll
            for (int c9 = 0; c9 < 9; ++c9)
                P2[c9 * 128 + kkA * 32 + lane] = hsum2(acc[c9]);
        }
        __syncthreads();

        // P5: layer2 reduce — 288 outs -> A2 (wid 0-7 do cell=wid, wid0 also cell 8)
        {
            int cell = wid;
            const float* p = P2 + cell * 128 + lane;
            float s = (p[0] + p[32]) + (p[64] + p[96]) + b2r;
            s = fmaxf(s, 0.f);
            int r = cell / 3, c = cell % 3;
            if (fy + r > 99 || fx + c > 99) s = 0.f;
            A2[cell * 32 + lane] = s;
            if (wid == 0) {
                const float* p8 = P2 + 8 * 128 + lane;
                float s8 = (p8[0] + p8[32]) + (p8[64] + p8[96]) + b2r;
                s8 = fmaxf(s8, 0.f);
                if (fy + 2 > 99 || fx + 2 > 99) s8 = 0.f;
                A2[8 * 32 + lane] = s8;
            }
        }
        __syncthreads();

        // P6: layer3 partials — warps 0-3 (kk = wid), 4 cells
        if (wid < 4) {
            const ulonglong2* base3 =
                (const ulonglong2*)(A2 + (khA * 3 + kwA) * 32);
            ull acc[4];
            #pragma unroll
            for (int c4 = 0; c4 < 4; ++c4) acc[c4] = 0ULL;
            #pragma unroll
            for (int q = 0; q < 8; ++q) {
                #pragma unroll
                for (int c4 = 0; c4 < 4; ++c4) {
                    ulonglong2 av = base3[((c4 >> 1) * 3 + (c4 & 1)) * 8 + q];
                    ffma2(acc[c4], av.x, wrB[2 * q]);
                    ffma2(acc[c4], av.y, wrB[2 * q + 1]);
                }
            }
            #pragma unroll
            for (int c4 = 0; c4 < 4; ++c4)
                P3[c4 * 128 + kkA * 32 + lane] = hsum2(acc[c4]);
        }
        __syncthreads();

        // Tail (warps 0-2): bilinear -> X -> GI -> H -> GH || head/Y/Q4
        if (tid < 96) {
            if (tid < 32) {
                float ay = Q4[2], ax = Q4[3];
                float o[4];
                #pragma unroll
                for (int c4 = 0; c4 < 4; ++c4) {
                    const float* p = P3 + c4 * 128 + lane;
                    float v = (p[0] + p[32]) + (p[64] + p[96]) + b3r;
                    v = fmaxf(v, 0.f);
                    if (fy + (c4 >> 1) > 99 || fx + (c4 & 1) > 99) v = 0.f;
                    o[c4] = v;
                }
                float top = o[0] + ax * (o[1] - o[0]);
                float bot = o[2] + ax * (o[3] - o[2]);
                X[2 + lane] = top + ay * (bot - top);
                if (lane < 2) X[lane] = Y[lane];
            }
            BARS(2, 96);

            // GI matvec (96 threads)
            {
                ull a0 = 0ULL, a1 = 0ULL;
                const ulonglong2* wr = (const ulonglong2*)(DWIH + tid * 36);
                const ulonglong2* xp = (const ulonglong2*)X;
                #pragma unroll
                for (int k = 0; k < 8; ++k) {
                    ulonglong2 wv = wr[k];
                    ulonglong2 xv = xp[k];
                    ffma2(a0, xv.x, wv.x);
                    ffma2(a1, xv.y, wv.y);
                }
                ull wl = *(const ull*)(DWIH + tid * 36 + 32);
                ull xl = *(const ull*)(X + 32);
                ffma2(a0, xl, wl);
                GI[tid] = DBIH[tid] + hsum2(a0) + hsum2(a1);
            }
            BARS(2, 96);

            if (tid < 32) {
                float r  = fsig_(GI[tid] + GH[tid]);
                float zg = fsig_(GI[32 + tid] + GH[32 + tid]);
                float n  = ftanh_(GI[64 + tid] + r * GH[64 + tid]);
                H[tid] = (1.f - zg) * n + zg * H[tid];
            }
            BARS(2, 96);

            if (tid >= 32) {
                // warps 1-2: GH for next step (rows 0..63 + rows 64..95)
                int j = tid - 32;
                {
                    ull g0 = 0ULL, g1 = 0ULL;
                    const ulonglong2* hr = (const ulonglong2*)(DWHH + j * 36);
                    const ulonglong2* hp = (const ulonglong2*)H;
                    #pragma unroll
                    for (int k = 0; k < 8; ++k) {
                        ulonglong2 wv = hr[k];
                        ulonglong2 hv = hp[k];
                        ffma2(g0, hv.x, wv.x);
                        ffma2(g1, hv.y, wv.y);
                    }
                    GH[j] = DBHH[j] + hsum2(g0) + hsum2(g1);
                }
                if (j < 32) {
                    int j2 = j + 64;
                    ull g0 = 0ULL, g1 = 0ULL;
                    const ulonglong2* hr = (const ulonglong2*)(DWHH + j2 * 36);
                    const ulonglong2* hp = (const ulonglong2*)H;
                    #pragma unroll
                    for (int k = 0; k < 8; ++k) {
                        ulonglong2 wv = hr[k];
                        ulonglong2 hv = hp[k];
                        ffma2(g0, hv.x, wv.x);
                        ffma2(g1, hv.y, wv.y);
                    }
                    GH[j2] = DBHH[j2] + hsum2(g0) + hsum2(g1);
                }
            } else {
                // warp 0: head + Y-update + Q4
                int o = tid >> 3, k0 = (tid & 7) * 4;
                const float* wr2 = WC + o * 32 + k0;
                const float* hr2 = H + k0;
                float part = wr2[0] * hr2[0];
                part = fmaf(wr2[1], hr2[1], part);
                part = fmaf(wr2[2], hr2[2], part);
                part = fmaf(wr2[3], hr2[3], part);
                #pragma unroll
                for (int off = 4; off; off >>= 1)
                    part += __shfl_xor_sync(0xffffffffu, part, off);
                float v = part + BC[o];
                float locv = __shfl_sync(0xffffffffu, v, (tid & 1) * 8);
                float spv  = __shfl_sync(0xffffffffu, v, 16 + (tid & 1) * 8);
                float yn = 0.f;
                if (tid < 2) {
                    float s  = fsoftplus_(spv);
                    float zt = ZB[t * 2 + tid];
                    yn = 2.f * Y[tid] - Y[2 + tid] + locv + s * zt;
                    out[(b * T_FUT + t) * 2 + tid] = yn;
                    logdet += flogf_(s);
                    Y[2 + tid] = Y[tid];
                    Y[tid] = yn;
                }
                float y0 = __shfl_sync(0xffffffffu, yn, 0);
                float y1 = __shfl_sync(0xffffffffu, yn, 1);
                if (tid == 0) {
                    float f0 = fminf(fmaxf(floorf(y0), 0.f), 98.f);
                    float f1 = fminf(fmaxf(floorf(y1), 0.f), 98.f);
                    Q4[0] = f0; Q4[1] = f1;
                    Q4[2] = fminf(fmaxf(y0 - f0, 0.f), 1.f);
                    Q4[3] = fminf(fmaxf(y1 - f1, 0.f), 1.f);
                }
            }
        }
        __syncthreads();   // Y/H/GH/Q4 ready for next step
    }

    if (tid < 2) LD[tid] = logdet;
    __syncthreads();
    if (tid == 0) out[B_N * T_FUT * 2 + b] = LD[0] + LD[1];
}

extern "C" void kernel_launch(void* const* d_in, const int* in_sizes, int n_in,
                              void* d_out, int out_size)
{
    const float* z    = (const float*)d_in[0];
    const float* pp   = (const float*)d_in[1];
    const float* lid  = (const float*)d_in[2];
    const float* c0w  = (const float*)d_in[3];
    const float* c0b  = (const float*)d_in[4];
    const float* c1w  = (const float*)d_in[5];
    const float* c1b  = (const float*)d_in[6];
    const float* c2w  = (const float*)d_in[7];
    const float* c2b  = (const float*)d_in[8];
    const float* c3w  = (const float*)d_in[9];
    const float* c3b  = (const float*)d_in[10];
    const float* ewih = (const float*)d_in[11];
    const float* ewhh = (const float*)d_in[12];
    const float* ebih = (const float*)d_in[13];
    const float* ebhh = (const float*)d_in[14];
    const float* dwih = (const float*)d_in[15];
    const float* dwhh = (const float*)d_in[16];
    const float* dbih = (const float*)d_in[17];
    const float* dbhh = (const float*)d_in[18];
    const float* w1   = (const float*)d_in[19];
    const float* b1   = (const float*)d_in[20];
    const float* w2   = (const float*)d_in[21];
    const float* b2   = (const float*)d_in[22];
    float* out = (float*)d_out;

    cudaFuncSetAttribute(r2p2_kernel,
                         cudaFuncAttributeMaxDynamicSharedMemorySize, SMEM_BYTES);

    r2p2_kernel<<<B_N, NT, SMEM_BYTES>>>(z, pp, lid,
        c0w, c0b, c1w, c1b, c2w, c2b, c3w, c3b,
        ewih, ewhh, ebih, ebhh, dwih, dwhh, dbih, dbhh,
        w1, b1, w2, b2, out);
}